// round 5
// baseline (speedup 1.0000x reference)
#include <cuda_runtime.h>
#include <cstdint>

static constexpr int T_IN  = 1048576;
static constexpr int T_OUT = 1048564;              // T_IN - 12
static constexpr int ROWS  = 32;                   // 8 * 4
static constexpr int VEC_PER_ROW = T_OUT / 4;      // 262141 output float4s per row
static constexpr int F4_PER_ROW  = T_IN / 4;       // 262144 input float4s per row
static constexpr long TOTAL_F4   = (long)ROWS * F4_PER_ROW;   // 8388608
static constexpr int VEC_TILE = 512;               // output float4s per tile
static constexpr int NTILES = ROWS * 512;          // 16384 tiles total
static constexpr int TILE_F4 = 515;                // input float4s per tile (halo 12 floats)
static constexpr int GRID = 1184;                  // 148 SMs x 8 blocks

__global__ __launch_bounds__(256)
void conv13_pipe(const float4* __restrict__ x4, float* __restrict__ out,
                 const float* __restrict__ fd, const float* __restrict__ gauss) {
    __shared__ float4 sx[2][TILE_F4 + 1];
    __shared__ float sc[13];

    const int t = threadIdx.x;

    // Compose 13-tap kernel (covered by the first in-loop __syncthreads()).
    if (t < 13) {
        float acc = 0.0f;
        #pragma unroll
        for (int i = 0; i < 5; ++i) {
            int j = t - i;
            if (j >= 0 && j < 9) acc = fmaf(__ldg(fd + i), __ldg(gauss + j), acc);
        }
        sc[t] = acc;
    }

    uint32_t sb[2];
    asm("{ .reg .u64 a; cvta.to.shared.u64 a, %1; cvt.u32.u64 %0, a; }"
        : "=r"(sb[0]) : "l"(&sx[0][0]));
    asm("{ .reg .u64 a; cvta.to.shared.u64 a, %1; cvt.u32.u64 %0, a; }"
        : "=r"(sb[1]) : "l"(&sx[1][0]));

    auto prefetch = [&](int tid, uint32_t s0) {
        int row  = tid >> 9;
        int tile = tid & 511;
        long gbase = (long)row * F4_PER_ROW + (long)tile * VEC_TILE;
        #pragma unroll
        for (int r = 0; r < 2; ++r) {
            int i = t + r * 256;
            long g4 = gbase + i;
            int sz = (g4 < TOTAL_F4) ? 16 : 0;   // zero-fill past end of x
            asm volatile("cp.async.cg.shared.global [%0], [%1], 16, %2;"
                         :: "r"(s0 + i * 16), "l"(x4 + g4), "r"(sz));
        }
        if (t < TILE_F4 - 512) {                 // i = 512..514
            int i = 512 + t;
            long g4 = gbase + i;
            int sz = (g4 < TOTAL_F4) ? 16 : 0;
            asm volatile("cp.async.cg.shared.global [%0], [%1], 16, %2;"
                         :: "r"(s0 + i * 16), "l"(x4 + g4), "r"(sz));
        }
    };

    int tid = blockIdx.x;
    if (tid >= NTILES) return;

    // Prologue: prefetch first tile into stage 0.
    prefetch(tid, sb[0]);
    asm volatile("cp.async.commit_group;");

    int s = 0;
    for (; tid < NTILES; tid += GRID) {
        int next = tid + GRID;
        if (next < NTILES) prefetch(next, sb[s ^ 1]);
        asm volatile("cp.async.commit_group;");
        asm volatile("cp.async.wait_group 1;");   // current tile's data arrived
        __syncthreads();

        const float4* __restrict__ buf = sx[s];
        const int row  = tid >> 9;
        const int tile = tid & 511;
        const int vb   = tile * VEC_TILE;

        #pragma unroll
        for (int r = 0; r < 2; ++r) {
            int v = t + r * 256;
            int gvec = vb + v;

            float4 q0 = buf[v], q1 = buf[v + 1], q2 = buf[v + 2], q3 = buf[v + 3];
            float xv[16] = {q0.x, q0.y, q0.z, q0.w,  q1.x, q1.y, q1.z, q1.w,
                            q2.x, q2.y, q2.z, q2.w,  q3.x, q3.y, q3.z, q3.w};

            float y0 = 0.f, y1 = 0.f, y2 = 0.f, y3 = 0.f;
            #pragma unroll
            for (int k = 0; k < 13; ++k) {
                float c = sc[k];
                y0 = fmaf(c, xv[k],     y0);
                y1 = fmaf(c, xv[k + 1], y1);
                y2 = fmaf(c, xv[k + 2], y2);
                y3 = fmaf(c, xv[k + 3], y3);
            }

            if (gvec < VEC_PER_ROW) {
                long o = (long)row * T_OUT + (long)gvec * 4;
                __stcs(reinterpret_cast<float4*>(out + o),
                       make_float4(y0, y1, y2, y3));
            }
        }

        __syncthreads();   // stage s free before it is overwritten next+1
        s ^= 1;
    }
}

extern "C" void kernel_launch(void* const* d_in, const int* in_sizes, int n_in,
                              void* d_out, int out_size) {
    const float4* x4   = (const float4*)d_in[0];
    const float* fd    = (const float*)d_in[1];
    const float* gauss = (const float*)d_in[2];
    float* out = (float*)d_out;

    conv13_pipe<<<GRID, 256>>>(x4, out, fd, gauss);
}

// round 6
// speedup vs baseline: 1.1361x; 1.1361x over previous
#include <cuda_runtime.h>
#include <cstdint>

static constexpr int T_IN  = 1048576;
static constexpr int T_OUT = 1048564;              // T_IN - 12
static constexpr int ROWS  = 32;                   // 8 * 4
static constexpr int VEC_PER_ROW = T_OUT / 4;      // 262141 output float4s per row
static constexpr int F4_PER_ROW  = T_IN / 4;       // 262144 input float4s per row
static constexpr long TOTAL_F4   = (long)ROWS * F4_PER_ROW;   // 8388608
static constexpr int VEC_TILE = 512;               // output float4s per tile
static constexpr int NTILES = ROWS * 512;          // 16384 tiles
static constexpr int TILE_F4 = 515;                // input float4s per tile (12-float halo)
static constexpr int GRID2 = NTILES / 2;           // 8192 blocks, 2 tiles each

__global__ __launch_bounds__(256)
void conv13_dual(const float4* __restrict__ x4, float* __restrict__ out,
                 const float* __restrict__ fd, const float* __restrict__ gauss) {
    __shared__ float4 sx[2][TILE_F4 + 1];
    __shared__ float sc[13];

    const int t = threadIdx.x;

    uint32_t sb0, sb1;
    asm("{ .reg .u64 a; cvta.to.shared.u64 a, %1; cvt.u32.u64 %0, a; }"
        : "=r"(sb0) : "l"(&sx[0][0]));
    asm("{ .reg .u64 a; cvta.to.shared.u64 a, %1; cvt.u32.u64 %0, a; }"
        : "=r"(sb1) : "l"(&sx[1][0]));

    auto prefetch = [&](int tid, uint32_t s0) {
        int row  = tid >> 9;
        int tile = tid & 511;
        long gbase = (long)row * F4_PER_ROW + (long)tile * VEC_TILE;
        #pragma unroll
        for (int r = 0; r < 2; ++r) {
            int i = t + r * 256;
            long g4 = gbase + i;
            int sz = (g4 < TOTAL_F4) ? 16 : 0;     // zero-fill past end of x
            asm volatile("cp.async.cg.shared.global [%0], [%1], 16, %2;"
                         :: "r"(s0 + i * 16), "l"(x4 + g4), "r"(sz));
        }
        if (t < TILE_F4 - 512) {                   // i = 512..514
            int i = 512 + t;
            long g4 = gbase + i;
            int sz = (g4 < TOTAL_F4) ? 16 : 0;
            asm volatile("cp.async.cg.shared.global [%0], [%1], 16, %2;"
                         :: "r"(s0 + i * 16), "l"(x4 + g4), "r"(sz));
        }
    };

    const int tid0 = blockIdx.x;
    const int tid1 = blockIdx.x + GRID2;

    // Both tiles' loads go in flight immediately.
    prefetch(tid0, sb0);
    asm volatile("cp.async.commit_group;");
    prefetch(tid1, sb1);
    asm volatile("cp.async.commit_group;");

    // Compose the 13-tap composite kernel while copies fly.
    if (t < 13) {
        float acc = 0.0f;
        #pragma unroll
        for (int i = 0; i < 5; ++i) {
            int j = t - i;
            if (j >= 0 && j < 9) acc = fmaf(__ldg(fd + i), __ldg(gauss + j), acc);
        }
        sc[t] = acc;
    }

    auto compute = [&](int tid, const float4* __restrict__ buf) {
        const int row  = tid >> 9;
        const int tile = tid & 511;
        const int vb   = tile * VEC_TILE;
        #pragma unroll
        for (int r = 0; r < 2; ++r) {
            int v = t + r * 256;
            int gvec = vb + v;

            float4 q0 = buf[v], q1 = buf[v + 1], q2 = buf[v + 2], q3 = buf[v + 3];
            float xv[16] = {q0.x, q0.y, q0.z, q0.w,  q1.x, q1.y, q1.z, q1.w,
                            q2.x, q2.y, q2.z, q2.w,  q3.x, q3.y, q3.z, q3.w};

            float y0 = 0.f, y1 = 0.f, y2 = 0.f, y3 = 0.f;
            #pragma unroll
            for (int k = 0; k < 13; ++k) {
                float c = sc[k];
                y0 = fmaf(c, xv[k],     y0);
                y1 = fmaf(c, xv[k + 1], y1);
                y2 = fmaf(c, xv[k + 2], y2);
                y3 = fmaf(c, xv[k + 3], y3);
            }

            if (gvec < VEC_PER_ROW) {
                long o = (long)row * T_OUT + (long)gvec * 4;
                __stcs(reinterpret_cast<float4*>(out + o),
                       make_float4(y0, y1, y2, y3));
            }
        }
    };

    asm volatile("cp.async.wait_group 1;");   // tile0 resident (tile1 still in flight)
    __syncthreads();
    compute(tid0, sx[0]);

    asm volatile("cp.async.wait_group 0;");   // tile1 resident
    __syncthreads();
    compute(tid1, sx[1]);
}

extern "C" void kernel_launch(void* const* d_in, const int* in_sizes, int n_in,
                              void* d_out, int out_size) {
    const float4* x4   = (const float4*)d_in[0];
    const float* fd    = (const float*)d_in[1];
    const float* gauss = (const float*)d_in[2];
    float* out = (float*)d_out;

    conv13_dual<<<GRID2, 256>>>(x4, out, fd, gauss);
}